// round 1
// baseline (speedup 1.0000x reference)
#include <cuda_runtime.h>
#include <cuda_bf16.h>
#include <math.h>

// Problem constants: B=4, T=2048, C=768, H=12, D=64
#define Bv 4
#define Tv 2048
#define Cv 768
#define Hv 12
#define Dv 64
#define C3v (3 * Cv)     // 2304
#define Mv (Bv * Tv)     // 8192

// Scratch (device globals — no allocation allowed)
__device__ float g_qkv[(size_t)Mv * C3v];   // [B*T, 3C]
__device__ float g_y[(size_t)Mv * Cv];      // [B*T, C]

// ---------------------------------------------------------------------------
// Tiled SGEMM with bias: C[M,N] = A[M,K] @ B[K,N] + bias[N]
// BM=BN=128, BK=16, 256 threads, 8x8 per-thread tile.
// Requires M%128==0, N%128==0, K%16==0 (true for all our shapes).
// ---------------------------------------------------------------------------
__global__ __launch_bounds__(256, 2)
void sgemm_bias(const float* __restrict__ A, const float* __restrict__ Bm,
                const float* __restrict__ bias, float* __restrict__ Cm,
                int M, int N, int K) {
    constexpr int BM = 128, BN = 128, BK = 16, TM = 8, TN = 8;
    __shared__ float As[BK][BM];   // transposed A tile
    __shared__ float Bs[BK][BN];

    const int tid = threadIdx.x;
    const int bx = blockIdx.x;     // N tile
    const int by = blockIdx.y;     // M tile

    const float* Ablk = A + (size_t)by * BM * K;
    const float* Bblk = Bm + (size_t)bx * BN;

    const int tcol = tid % (BN / TN);   // 0..15
    const int trow = tid / (BN / TN);   // 0..15

    const int aRow = tid / (BK / 4);        // 0..63
    const int aCol = (tid % (BK / 4)) * 4;  // 0,4,8,12
    const int bRow = tid / (BN / 4);        // 0..7
    const int bCol = (tid % (BN / 4)) * 4;  // 0..124

    float acc[TM][TN];
    #pragma unroll
    for (int i = 0; i < TM; i++)
        #pragma unroll
        for (int j = 0; j < TN; j++) acc[i][j] = 0.f;

    for (int k0 = 0; k0 < K; k0 += BK) {
        #pragma unroll
        for (int i = 0; i < BM; i += 64) {
            float4 v = *(const float4*)(Ablk + (size_t)(aRow + i) * K + k0 + aCol);
            As[aCol + 0][aRow + i] = v.x;
            As[aCol + 1][aRow + i] = v.y;
            As[aCol + 2][aRow + i] = v.z;
            As[aCol + 3][aRow + i] = v.w;
        }
        #pragma unroll
        for (int i = 0; i < BK; i += 8) {
            float4 v = *(const float4*)(Bblk + (size_t)(k0 + bRow + i) * N + bCol);
            *(float4*)&Bs[bRow + i][bCol] = v;
        }
        __syncthreads();

        #pragma unroll
        for (int kk = 0; kk < BK; kk++) {
            float ra[TM], rb[TN];
            #pragma unroll
            for (int i = 0; i < TM; i += 4) {
                float4 v = *(const float4*)&As[kk][trow * TM + i];
                ra[i] = v.x; ra[i + 1] = v.y; ra[i + 2] = v.z; ra[i + 3] = v.w;
            }
            #pragma unroll
            for (int j = 0; j < TN; j += 4) {
                float4 v = *(const float4*)&Bs[kk][tcol * TN + j];
                rb[j] = v.x; rb[j + 1] = v.y; rb[j + 2] = v.z; rb[j + 3] = v.w;
            }
            #pragma unroll
            for (int i = 0; i < TM; i++)
                #pragma unroll
                for (int j = 0; j < TN; j++)
                    acc[i][j] = fmaf(ra[i], rb[j], acc[i][j]);
        }
        __syncthreads();
    }

    #pragma unroll
    for (int i = 0; i < TM; i++) {
        const int r = by * BM + trow * TM + i;
        #pragma unroll
        for (int j = 0; j < TN; j += 4) {
            const int c = bx * BN + tcol * TN + j;
            float4 v;
            v.x = acc[i][j + 0] + bias[c + 0];
            v.y = acc[i][j + 1] + bias[c + 1];
            v.z = acc[i][j + 2] + bias[c + 2];
            v.w = acc[i][j + 3] + bias[c + 3];
            *(float4*)(Cm + (size_t)r * N + c) = v;
        }
    }
}

// ---------------------------------------------------------------------------
// Causal flash attention (fp32, online softmax).
// grid = (T/128, H, B), 128 threads. Each thread owns one q row:
// q[64] and acc[64] live in registers; K/V tiles (64x64) in smem, read as
// warp-uniform float4 broadcasts (1 LDS.128 : 4 FMA ratio -> FMA-bound).
// ---------------------------------------------------------------------------
__global__ __launch_bounds__(128)
void attn_kernel(const float* __restrict__ qkv, float* __restrict__ y) {
    constexpr int BQ = 128, BKV = 64;
    const int qt = blockIdx.x;
    const int h  = blockIdx.y;
    const int b  = blockIdx.z;
    const int tid = threadIdx.x;
    const int r = qt * BQ + tid;                    // q row within sequence

    const float* base = qkv + (size_t)b * Tv * C3v;

    __shared__ float Ks[BKV][Dv];
    __shared__ float Vs[BKV][Dv];

    float q[Dv], acc[Dv];
    const float* qrow = base + (size_t)r * C3v + h * Dv;
    const float sc = 0.125f;                        // 1/sqrt(64)
    #pragma unroll
    for (int d = 0; d < Dv; d += 4) {
        float4 v = *(const float4*)(qrow + d);
        q[d] = v.x * sc; q[d + 1] = v.y * sc; q[d + 2] = v.z * sc; q[d + 3] = v.w * sc;
    }
    #pragma unroll
    for (int d = 0; d < Dv; d++) acc[d] = 0.f;

    float m = -INFINITY, l = 0.f;

    const int kmax = qt * BQ + BQ;                  // keys needed by this block
    for (int kb = 0; kb < kmax; kb += BKV) {
        // cooperative K/V tile load
        for (int idx = tid; idx < BKV * (Dv / 4); idx += BQ) {
            const int j = idx / (Dv / 4);
            const int d4 = (idx % (Dv / 4)) * 4;
            const float* krow = base + (size_t)(kb + j) * C3v + h * Dv;
            *(float4*)&Ks[j][d4] = *(const float4*)(krow + Cv + d4);       // K
            *(float4*)&Vs[j][d4] = *(const float4*)(krow + 2 * Cv + d4);   // V
        }
        __syncthreads();

        if (kb <= r) {
            #pragma unroll 1
            for (int j0 = 0; j0 < BKV; j0 += 16) {
                if (kb + j0 > r) break;             // fully-masked chunk
                float s[16];
                float cmax = -INFINITY;
                #pragma unroll
                for (int jj = 0; jj < 16; jj++) {
                    const int j = j0 + jj;
                    float dot = 0.f;
                    #pragma unroll
                    for (int d = 0; d < Dv; d += 4) {
                        float4 kv = *(const float4*)&Ks[j][d];
                        dot = fmaf(q[d], kv.x, dot);
                        dot = fmaf(q[d + 1], kv.y, dot);
                        dot = fmaf(q[d + 2], kv.z, dot);
                        dot = fmaf(q[d + 3], kv.w, dot);
                    }
                    s[jj] = (kb + j <= r) ? dot : -INFINITY;
                    cmax = fmaxf(cmax, s[jj]);
                }
                const float mnew = fmaxf(m, cmax);
                const float corr = __expf(m - mnew);
                l *= corr;
                #pragma unroll
                for (int d = 0; d < Dv; d++) acc[d] *= corr;
                #pragma unroll
                for (int jj = 0; jj < 16; jj++) {
                    const int j = j0 + jj;
                    const float p = (s[jj] == -INFINITY) ? 0.f : __expf(s[jj] - mnew);
                    l += p;
                    #pragma unroll
                    for (int d = 0; d < Dv; d += 4) {
                        float4 vv = *(const float4*)&Vs[j][d];
                        acc[d]     = fmaf(p, vv.x, acc[d]);
                        acc[d + 1] = fmaf(p, vv.y, acc[d + 1]);
                        acc[d + 2] = fmaf(p, vv.z, acc[d + 2]);
                        acc[d + 3] = fmaf(p, vv.w, acc[d + 3]);
                    }
                }
                m = mnew;
            }
        }
        __syncthreads();
    }

    // write y[b, r, h*D + d] = acc/l   (l >= 1: diagonal always unmasked)
    const float inv_l = 1.f / l;
    float* yrow = y + ((size_t)b * Tv + r) * Cv + h * Dv;
    #pragma unroll
    for (int d = 0; d < Dv; d += 4) {
        float4 v;
        v.x = acc[d] * inv_l;
        v.y = acc[d + 1] * inv_l;
        v.z = acc[d + 2] * inv_l;
        v.w = acc[d + 3] * inv_l;
        *(float4*)(yrow + d) = v;
    }
}

extern "C" void kernel_launch(void* const* d_in, const int* in_sizes, int n_in,
                              void* d_out, int out_size) {
    const float* x      = (const float*)d_in[0];
    const float* w_attn = (const float*)d_in[1];
    const float* b_attn = (const float*)d_in[2];
    const float* w_proj = (const float*)d_in[3];
    const float* b_proj = (const float*)d_in[4];
    float* out = (float*)d_out;

    float* qkv = nullptr;
    float* y   = nullptr;
    cudaGetSymbolAddress((void**)&qkv, g_qkv);
    cudaGetSymbolAddress((void**)&y,   g_y);

    // 1) qkv = x @ w_attn + b_attn    [8192 x 2304]
    sgemm_bias<<<dim3(C3v / 128, Mv / 128), 256>>>(x, w_attn, b_attn, qkv, Mv, C3v, Cv);
    // 2) causal flash attention -> y  [8192 x 768]
    attn_kernel<<<dim3(Tv / 128, Hv, Bv), 128>>>(qkv, y);
    // 3) out = y @ w_proj + b_proj    [8192 x 768]
    sgemm_bias<<<dim3(Cv / 128, Mv / 128), 256>>>(y, w_proj, b_proj, out, Mv, Cv, Cv);
}